// round 14
// baseline (speedup 1.0000x reference)
#include <cuda_runtime.h>
#include <cuda_fp16.h>
#include <cstdint>

#define Nn 50000
#define Ee 1600000
#define CC 128
#define HH 8
#define SCAN_B 1024
#define NBLK ((Nn + SCAN_B - 1) / SCAN_B)   // 49

// ---- scratch (static __device__: allocation-free, zero-initialized) ----
__device__ __half g_embh[Nn * CC];   // 12.8 MB (fp16 message values)
__device__ float g_left[Nn * HH];
__device__ float g_right[Nn * HH];
__device__ int   g_deg[Nn];          // zero at load; re-zeroed by k_scanA each call
__device__ int   g_off[Nn + 1];
__device__ int   g_csr[Ee];          // 6.4 MB
__device__ int   g_rank[Ee];         // 6.4 MB (edge rank within its dst)
__device__ int   g_bsum[NBLK];

// ------------------------------------------------------------------
// K1: emb = X @ W^T via mma.sync m16n8k16 (f16 in, f32 acc)
//     + fused left/right logits
//     + fused dst-degree histogram that records each edge's rank.
// ------------------------------------------------------------------
__global__ void k_gemm(const float* __restrict__ X, const float* __restrict__ W,
                       const float* __restrict__ aL, const float* __restrict__ aR,
                       const int* __restrict__ ei, int e, int n) {
    __shared__ __half Xsh[128][72];   // stride 72 halves -> conflict-free
    __shared__ __half Wsh[128][72];
    __shared__ float  aLs[16][8];
    __shared__ float  aRs[16][8];

    const int tid  = threadIdx.x;
    const int lane = tid & 31;
    const int wid  = tid >> 5;
    const int q    = lane & 3;
    const int g    = lane >> 2;
    const int m0   = blockIdx.x * 128;

    if (tid < 128) {
        aLs[tid >> 3][tid & 7] = aL[tid];
        aRs[tid >> 3][tid & 7] = aR[tid];
    }

    float acc[16][4];
    #pragma unroll
    for (int nt = 0; nt < 16; nt++) {
        acc[nt][0] = 0.f; acc[nt][1] = 0.f; acc[nt][2] = 0.f; acc[nt][3] = 0.f;
    }

    for (int kc = 0; kc < CC; kc += 64) {
        #pragma unroll
        for (int it = 0; it < 8; it++) {
            int idx = tid + it * 256;
            int r   = idx >> 4;
            int c4  = (idx & 15) * 4;
            int node = m0 + r;
            float4 v = (node < n) ? *(const float4*)&X[node * CC + kc + c4]
                                  : make_float4(0.f, 0.f, 0.f, 0.f);
            *(__half2*)&Xsh[r][c4]     = __floats2half2_rn(v.x, v.y);
            *(__half2*)&Xsh[r][c4 + 2] = __floats2half2_rn(v.z, v.w);
        }
        #pragma unroll
        for (int it = 0; it < 8; it++) {
            int idx = tid + it * 256;
            int r   = idx >> 4;
            int c4  = (idx & 15) * 4;
            float4 v = *(const float4*)&W[r * CC + kc + c4];
            *(__half2*)&Wsh[r][c4]     = __floats2half2_rn(v.x, v.y);
            *(__half2*)&Wsh[r][c4 + 2] = __floats2half2_rn(v.z, v.w);
        }
        __syncthreads();

        #pragma unroll
        for (int ks = 0; ks < 4; ks++) {
            const int kb   = ks * 16;
            const int arow = wid * 16 + g;
            const int kcol = kb + q * 2;
            uint32_t a0 = *(const uint32_t*)&Xsh[arow][kcol];
            uint32_t a1 = *(const uint32_t*)&Xsh[arow + 8][kcol];
            uint32_t a2 = *(const uint32_t*)&Xsh[arow][kcol + 8];
            uint32_t a3 = *(const uint32_t*)&Xsh[arow + 8][kcol + 8];
            #pragma unroll
            for (int nt = 0; nt < 16; nt++) {
                const int brow = nt * 8 + g;
                uint32_t b0 = *(const uint32_t*)&Wsh[brow][kcol];
                uint32_t b1 = *(const uint32_t*)&Wsh[brow][kcol + 8];
                asm volatile(
                    "mma.sync.aligned.m16n8k16.row.col.f32.f16.f16.f32 "
                    "{%0,%1,%2,%3}, {%4,%5,%6,%7}, {%8,%9}, {%0,%1,%2,%3};\n"
                    : "+f"(acc[nt][0]), "+f"(acc[nt][1]), "+f"(acc[nt][2]), "+f"(acc[nt][3])
                    : "r"(a0), "r"(a1), "r"(a2), "r"(a3), "r"(b0), "r"(b1));
            }
        }
        __syncthreads();
    }

    const int r0    = wid * 16 + g;
    const int node0 = m0 + r0;
    const int node1 = node0 + 8;

    #pragma unroll
    for (int nt = 0; nt < 16; nt++) {
        int c = nt * 8 + q * 2;
        if (node0 < n) *(__half2*)&g_embh[node0 * CC + c] = __floats2half2_rn(acc[nt][0], acc[nt][1]);
        if (node1 < n) *(__half2*)&g_embh[node1 * CC + c] = __floats2half2_rn(acc[nt][2], acc[nt][3]);
    }

    float l0v[HH], r0v[HH], l1v[HH], r1v[HH];
    #pragma unroll
    for (int h = 0; h < HH; h++) {
        const int ntA = 2 * h, ntB = 2 * h + 1;
        const int cA = q * 2;
        const int cB = 8 + q * 2;
        float lA = aLs[cA][h],     lA1 = aLs[cA + 1][h];
        float lB = aLs[cB][h],     lB1 = aLs[cB + 1][h];
        float rA = aRs[cA][h],     rA1 = aRs[cA + 1][h];
        float rB = aRs[cB][h],     rB1 = aRs[cB + 1][h];

        float l0 = acc[ntA][0] * lA + acc[ntA][1] * lA1 + acc[ntB][0] * lB + acc[ntB][1] * lB1;
        float r0s = acc[ntA][0] * rA + acc[ntA][1] * rA1 + acc[ntB][0] * rB + acc[ntB][1] * rB1;
        float l1 = acc[ntA][2] * lA + acc[ntA][3] * lA1 + acc[ntB][2] * lB + acc[ntB][3] * lB1;
        float r1s = acc[ntA][2] * rA + acc[ntA][3] * rA1 + acc[ntB][2] * rB + acc[ntB][3] * rB1;

        l0  += __shfl_xor_sync(0xffffffffu, l0, 1);
        l0  += __shfl_xor_sync(0xffffffffu, l0, 2);
        r0s += __shfl_xor_sync(0xffffffffu, r0s, 1);
        r0s += __shfl_xor_sync(0xffffffffu, r0s, 2);
        l1  += __shfl_xor_sync(0xffffffffu, l1, 1);
        l1  += __shfl_xor_sync(0xffffffffu, l1, 2);
        r1s += __shfl_xor_sync(0xffffffffu, r1s, 1);
        r1s += __shfl_xor_sync(0xffffffffu, r1s, 2);

        l0v[h] = l0; r0v[h] = r0s; l1v[h] = l1; r1v[h] = r1s;
    }
    if (node0 < n) {
        *(float2*)&g_left [node0 * HH + 2 * q] = make_float2(l0v[2 * q], l0v[2 * q + 1]);
        *(float2*)&g_right[node0 * HH + 2 * q] = make_float2(r0v[2 * q], r0v[2 * q + 1]);
    }
    if (node1 < n) {
        *(float2*)&g_left [node1 * HH + 2 * q] = make_float2(l1v[2 * q], l1v[2 * q + 1]);
        *(float2*)&g_right[node1 * HH + 2 * q] = make_float2(r1v[2 * q], r1v[2 * q + 1]);
    }

    // ---- fused histogram: count dst degrees AND record each edge's rank ----
    const int stride = gridDim.x * blockDim.x;
    for (int i = blockIdx.x * blockDim.x + tid; i < e; i += stride) {
        int dst = ei[e + i];
        g_rank[i] = atomicAdd(&g_deg[dst], 1);
    }
}

// ------------------------------------------------------------------
// K3: hierarchical exclusive scan (scanA re-zeros g_deg for next call;
//     scanC redundantly scans the 49 block sums, no scanB kernel)
// ------------------------------------------------------------------
__device__ __forceinline__ int block_scan_incl(int v, int tid, int* wsums) {
    int x = v;
    #pragma unroll
    for (int d = 1; d < 32; d <<= 1) {
        int y = __shfl_up_sync(0xffffffffu, x, d);
        if ((tid & 31) >= d) x += y;
    }
    if ((tid & 31) == 31) wsums[tid >> 5] = x;
    __syncthreads();
    if (tid < 32) {
        int s = wsums[tid];
        #pragma unroll
        for (int d = 1; d < 32; d <<= 1) {
            int y = __shfl_up_sync(0xffffffffu, s, d);
            if (tid >= d) s += y;
        }
        wsums[tid] = s;
    }
    __syncthreads();
    int wp = (tid >= 32) ? wsums[(tid >> 5) - 1] : 0;
    return x + wp;
}

__global__ void k_scanA(int n) {
    __shared__ int wsums[32];
    int tid = threadIdx.x;
    int i = blockIdx.x * SCAN_B + tid;
    int v = (i < n) ? g_deg[i] : 0;
    if (i < n) g_deg[i] = 0;              // leave histogram clean for next call
    int incl = block_scan_incl(v, tid, wsums);
    if (i < n) g_off[i] = incl - v;
    if (tid == SCAN_B - 1) g_bsum[blockIdx.x] = incl;
}

__global__ void k_scanC(int n) {
    __shared__ int wsums[32];
    __shared__ int bxs[NBLK];
    __shared__ int total_sh;
    int tid = threadIdx.x;

    int v = (tid < NBLK) ? g_bsum[tid] : 0;
    int incl = block_scan_incl(v, tid, wsums);
    if (tid < NBLK) bxs[tid] = incl - v;
    if (tid == NBLK - 1) total_sh = incl;
    __syncthreads();

    int i = blockIdx.x * SCAN_B + tid;
    if (i < n) g_off[i] += bxs[blockIdx.x];
    if (blockIdx.x == gridDim.x - 1 && tid == 0) g_off[n] = total_sh;
}

// ------------------------------------------------------------------
// K4: atomic-free scatter: pos = off[dst] + rank[i]
// ------------------------------------------------------------------
__global__ void k_scatter(const int* __restrict__ ei, int e) {
    int i = blockIdx.x * blockDim.x + threadIdx.x;
    if (i < e) {
        int dst = ei[e + i];
        g_csr[g_off[dst] + g_rank[i]] = ei[i];
    }
}

// ------------------------------------------------------------------
// K5: aggregation, 8-edge batches (compiler-scheduled load batching).
// One warp per dst node; lane owns 4 channels (head = lane>>2).
// ------------------------------------------------------------------
__global__ void k_agg(const float* __restrict__ bias, float* __restrict__ out, int n) {
    int warp = (blockIdx.x * blockDim.x + threadIdx.x) >> 5;
    int lane = threadIdx.x & 31;
    if (warp >= n) return;

    const int h = lane >> 2;
    const float rv = g_right[warp * HH + h];
    const int s0 = g_off[warp], s1 = g_off[warp + 1];
    const unsigned em_off = lane * 4;

    float4 acc = make_float4(0.f, 0.f, 0.f, 0.f);
    float sumw = 0.f;

    for (int base = s0; base < s1; base += 32) {
        int idx = base + lane;
        int sv  = (idx < s1) ? g_csr[idx] : 0;
        int cnt = min(32, s1 - base);

        int j = 0;
        for (; j + 8 <= cnt; j += 8) {
            int   s[8]; float lv[8]; uint2 r[8];
            #pragma unroll
            for (int u = 0; u < 8; u++) s[u] = __shfl_sync(0xffffffffu, sv, j + u);
            #pragma unroll
            for (int u = 0; u < 8; u++) lv[u] = g_left[s[u] * HH + h];
            #pragma unroll
            for (int u = 0; u < 8; u++) r[u] = *(const uint2*)&g_embh[s[u] * CC + em_off];
            #pragma unroll
            for (int u = 0; u < 8; u++) {
                float e = lv[u] + rv;
                e = (e >= 0.f) ? e : 0.2f * e;
                float w = __expf(e);
                float2 f0 = __half22float2(*(__half2*)&r[u].x);
                float2 f1 = __half22float2(*(__half2*)&r[u].y);
                sumw  += w;
                acc.x += w * f0.x; acc.y += w * f0.y;
                acc.z += w * f1.x; acc.w += w * f1.y;
            }
        }
        for (; j < cnt; j++) {
            int s = __shfl_sync(0xffffffffu, sv, j);
            float l = g_left[s * HH + h];
            uint2 raw = *(const uint2*)&g_embh[s * CC + em_off];
            float e = l + rv;
            e = (e >= 0.f) ? e : 0.2f * e;
            float w = __expf(e);
            float2 f0 = __half22float2(*(__half2*)&raw.x);
            float2 f1 = __half22float2(*(__half2*)&raw.y);
            sumw  += w;
            acc.x += w * f0.x; acc.y += w * f0.y;
            acc.z += w * f1.x; acc.w += w * f1.y;
        }
    }

    float inv = (sumw > 0.f) ? (1.f / sumw) : 0.f;
    int c = lane * 4;
    float4 o;
    o.x = acc.x * inv + bias[c + 0];
    o.y = acc.y * inv + bias[c + 1];
    o.z = acc.z * inv + bias[c + 2];
    o.w = acc.w * inv + bias[c + 3];
    *(float4*)&out[warp * CC + c] = o;
}

// ------------------------------------------------------------------
extern "C" void kernel_launch(void* const* d_in, const int* in_sizes, int n_in,
                              void* d_out, int out_size) {
    const float* X    = (const float*)d_in[0];
    const int*   EI   = (const int*)d_in[1];
    const float* W    = (const float*)d_in[2];
    const float* aL   = (const float*)d_in[3];
    const float* aR   = (const float*)d_in[4];
    const float* bias = (const float*)d_in[5];
    float*       out  = (float*)d_out;

    const int n = in_sizes[0] / CC;   // 50000
    const int e = in_sizes[1] / 2;    // 1600000

    k_gemm   <<<(n + 127) / 128, 256>>>(X, W, aL, aR, EI, e, n);
    k_scanA  <<<NBLK, SCAN_B>>>(n);
    k_scanC  <<<NBLK, SCAN_B>>>(n);
    k_scatter<<<(e + 255) / 256, 256>>>(EI, e);
    k_agg    <<<(n * 32 + 255) / 256, 256>>>(bias, out, n);
}

// round 15
// speedup vs baseline: 1.0086x; 1.0086x over previous
#include <cuda_runtime.h>
#include <cuda_fp16.h>
#include <cstdint>

#define Nn 50000
#define Ee 1600000
#define CC 128
#define HH 8
#define SCAN_B 1024
#define NBLK ((Nn + SCAN_B - 1) / SCAN_B)   // 49

// ---- scratch (static __device__: allocation-free, zero-initialized) ----
__device__ __half g_embh[Nn * CC];   // 12.8 MB (fp16 message values)
__device__ float g_left[Nn * HH];
__device__ float g_right[Nn * HH];
__device__ int   g_deg[Nn];          // zero at load; re-zeroed by k_scanA each call
__device__ int   g_off[Nn + 1];
__device__ int   g_cur[Nn];
__device__ int   g_csr[Ee];          // 6.4 MB
__device__ int   g_bsum[NBLK];

// ------------------------------------------------------------------
// K1: emb = X @ W^T via mma.sync m16n8k16 (f16 in, f32 acc)
//     + fused left/right logits + fused dst-degree histogram (REDG).
// ------------------------------------------------------------------
__global__ void k_gemm(const float* __restrict__ X, const float* __restrict__ W,
                       const float* __restrict__ aL, const float* __restrict__ aR,
                       const int* __restrict__ ei, int e, int n) {
    __shared__ __half Xsh[128][72];   // stride 72 halves -> conflict-free
    __shared__ __half Wsh[128][72];
    __shared__ float  aLs[16][8];
    __shared__ float  aRs[16][8];

    const int tid  = threadIdx.x;
    const int lane = tid & 31;
    const int wid  = tid >> 5;
    const int q    = lane & 3;
    const int g    = lane >> 2;
    const int m0   = blockIdx.x * 128;

    if (tid < 128) {
        aLs[tid >> 3][tid & 7] = aL[tid];
        aRs[tid >> 3][tid & 7] = aR[tid];
    }

    float acc[16][4];
    #pragma unroll
    for (int nt = 0; nt < 16; nt++) {
        acc[nt][0] = 0.f; acc[nt][1] = 0.f; acc[nt][2] = 0.f; acc[nt][3] = 0.f;
    }

    for (int kc = 0; kc < CC; kc += 64) {
        #pragma unroll
        for (int it = 0; it < 8; it++) {
            int idx = tid + it * 256;
            int r   = idx >> 4;
            int c4  = (idx & 15) * 4;
            int node = m0 + r;
            float4 v = (node < n) ? *(const float4*)&X[node * CC + kc + c4]
                                  : make_float4(0.f, 0.f, 0.f, 0.f);
            *(__half2*)&Xsh[r][c4]     = __floats2half2_rn(v.x, v.y);
            *(__half2*)&Xsh[r][c4 + 2] = __floats2half2_rn(v.z, v.w);
        }
        #pragma unroll
        for (int it = 0; it < 8; it++) {
            int idx = tid + it * 256;
            int r   = idx >> 4;
            int c4  = (idx & 15) * 4;
            float4 v = *(const float4*)&W[r * CC + kc + c4];
            *(__half2*)&Wsh[r][c4]     = __floats2half2_rn(v.x, v.y);
            *(__half2*)&Wsh[r][c4 + 2] = __floats2half2_rn(v.z, v.w);
        }
        __syncthreads();

        #pragma unroll
        for (int ks = 0; ks < 4; ks++) {
            const int kb   = ks * 16;
            const int arow = wid * 16 + g;
            const int kcol = kb + q * 2;
            uint32_t a0 = *(const uint32_t*)&Xsh[arow][kcol];
            uint32_t a1 = *(const uint32_t*)&Xsh[arow + 8][kcol];
            uint32_t a2 = *(const uint32_t*)&Xsh[arow][kcol + 8];
            uint32_t a3 = *(const uint32_t*)&Xsh[arow + 8][kcol + 8];
            #pragma unroll
            for (int nt = 0; nt < 16; nt++) {
                const int brow = nt * 8 + g;
                uint32_t b0 = *(const uint32_t*)&Wsh[brow][kcol];
                uint32_t b1 = *(const uint32_t*)&Wsh[brow][kcol + 8];
                asm volatile(
                    "mma.sync.aligned.m16n8k16.row.col.f32.f16.f16.f32 "
                    "{%0,%1,%2,%3}, {%4,%5,%6,%7}, {%8,%9}, {%0,%1,%2,%3};\n"
                    : "+f"(acc[nt][0]), "+f"(acc[nt][1]), "+f"(acc[nt][2]), "+f"(acc[nt][3])
                    : "r"(a0), "r"(a1), "r"(a2), "r"(a3), "r"(b0), "r"(b1));
            }
        }
        __syncthreads();
    }

    const int r0    = wid * 16 + g;
    const int node0 = m0 + r0;
    const int node1 = node0 + 8;

    #pragma unroll
    for (int nt = 0; nt < 16; nt++) {
        int c = nt * 8 + q * 2;
        if (node0 < n) *(__half2*)&g_embh[node0 * CC + c] = __floats2half2_rn(acc[nt][0], acc[nt][1]);
        if (node1 < n) *(__half2*)&g_embh[node1 * CC + c] = __floats2half2_rn(acc[nt][2], acc[nt][3]);
    }

    float l0v[HH], r0v[HH], l1v[HH], r1v[HH];
    #pragma unroll
    for (int h = 0; h < HH; h++) {
        const int ntA = 2 * h, ntB = 2 * h + 1;
        const int cA = q * 2;
        const int cB = 8 + q * 2;
        float lA = aLs[cA][h],     lA1 = aLs[cA + 1][h];
        float lB = aLs[cB][h],     lB1 = aLs[cB + 1][h];
        float rA = aRs[cA][h],     rA1 = aRs[cA + 1][h];
        float rB = aRs[cB][h],     rB1 = aRs[cB + 1][h];

        float l0 = acc[ntA][0] * lA + acc[ntA][1] * lA1 + acc[ntB][0] * lB + acc[ntB][1] * lB1;
        float r0s = acc[ntA][0] * rA + acc[ntA][1] * rA1 + acc[ntB][0] * rB + acc[ntB][1] * rB1;
        float l1 = acc[ntA][2] * lA + acc[ntA][3] * lA1 + acc[ntB][2] * lB + acc[ntB][3] * lB1;
        float r1s = acc[ntA][2] * rA + acc[ntA][3] * rA1 + acc[ntB][2] * rB + acc[ntB][3] * rB1;

        l0  += __shfl_xor_sync(0xffffffffu, l0, 1);
        l0  += __shfl_xor_sync(0xffffffffu, l0, 2);
        r0s += __shfl_xor_sync(0xffffffffu, r0s, 1);
        r0s += __shfl_xor_sync(0xffffffffu, r0s, 2);
        l1  += __shfl_xor_sync(0xffffffffu, l1, 1);
        l1  += __shfl_xor_sync(0xffffffffu, l1, 2);
        r1s += __shfl_xor_sync(0xffffffffu, r1s, 1);
        r1s += __shfl_xor_sync(0xffffffffu, r1s, 2);

        l0v[h] = l0; r0v[h] = r0s; l1v[h] = l1; r1v[h] = r1s;
    }
    if (node0 < n) {
        *(float2*)&g_left [node0 * HH + 2 * q] = make_float2(l0v[2 * q], l0v[2 * q + 1]);
        *(float2*)&g_right[node0 * HH + 2 * q] = make_float2(r0v[2 * q], r0v[2 * q + 1]);
    }
    if (node1 < n) {
        *(float2*)&g_left [node1 * HH + 2 * q] = make_float2(l1v[2 * q], l1v[2 * q + 1]);
        *(float2*)&g_right[node1 * HH + 2 * q] = make_float2(r1v[2 * q], r1v[2 * q + 1]);
    }

    // ---- fused dst-degree histogram (return discarded -> REDG) ----
    const int stride = gridDim.x * blockDim.x;
    for (int i = blockIdx.x * blockDim.x + tid; i < e; i += stride)
        atomicAdd(&g_deg[ei[e + i]], 1);
}

// ------------------------------------------------------------------
// K3: hierarchical exclusive scan (scanA re-zeros g_deg for next call;
//     scanC redundantly scans the 49 block sums, no scanB kernel)
// ------------------------------------------------------------------
__device__ __forceinline__ int block_scan_incl(int v, int tid, int* wsums) {
    int x = v;
    #pragma unroll
    for (int d = 1; d < 32; d <<= 1) {
        int y = __shfl_up_sync(0xffffffffu, x, d);
        if ((tid & 31) >= d) x += y;
    }
    if ((tid & 31) == 31) wsums[tid >> 5] = x;
    __syncthreads();
    if (tid < 32) {
        int s = wsums[tid];
        #pragma unroll
        for (int d = 1; d < 32; d <<= 1) {
            int y = __shfl_up_sync(0xffffffffu, s, d);
            if (tid >= d) s += y;
        }
        wsums[tid] = s;
    }
    __syncthreads();
    int wp = (tid >= 32) ? wsums[(tid >> 5) - 1] : 0;
    return x + wp;
}

__global__ void k_scanA(int n) {
    __shared__ int wsums[32];
    int tid = threadIdx.x;
    int i = blockIdx.x * SCAN_B + tid;
    int v = (i < n) ? g_deg[i] : 0;
    if (i < n) g_deg[i] = 0;              // leave histogram clean for next call
    int incl = block_scan_incl(v, tid, wsums);
    if (i < n) g_off[i] = incl - v;
    if (tid == SCAN_B - 1) g_bsum[blockIdx.x] = incl;
}

__global__ void k_scanC(int n) {
    __shared__ int wsums[32];
    __shared__ int bxs[NBLK];
    __shared__ int total_sh;
    int tid = threadIdx.x;

    int v = (tid < NBLK) ? g_bsum[tid] : 0;
    int incl = block_scan_incl(v, tid, wsums);
    if (tid < NBLK) bxs[tid] = incl - v;
    if (tid == NBLK - 1) total_sh = incl;
    __syncthreads();

    int i = blockIdx.x * SCAN_B + tid;
    if (i < n) {
        int o = g_off[i] + bxs[blockIdx.x];
        g_off[i] = o;
        g_cur[i] = o;
    }
    if (blockIdx.x == gridDim.x - 1 && tid == 0) g_off[n] = total_sh;
}

// ------------------------------------------------------------------
// K4: scatter edges into CSR (by dst). 4 independent edges per thread
// (strided for coalescing) -> 4 ATOMG chains in flight per thread.
// ------------------------------------------------------------------
__global__ void k_scatter(const int* __restrict__ ei, int e) {
    const int t = blockIdx.x * blockDim.x + threadIdx.x;
    const int T = gridDim.x * blockDim.x;   // ~e/4 threads

    int i0 = t, i1 = t + T, i2 = t + 2 * T, i3 = t + 3 * T;
    int d0 = (i0 < e) ? ei[e + i0] : -1;
    int d1 = (i1 < e) ? ei[e + i1] : -1;
    int d2 = (i2 < e) ? ei[e + i2] : -1;
    int d3 = (i3 < e) ? ei[e + i3] : -1;
    int s0 = (i0 < e) ? ei[i0] : 0;
    int s1 = (i1 < e) ? ei[i1] : 0;
    int s2 = (i2 < e) ? ei[i2] : 0;
    int s3 = (i3 < e) ? ei[i3] : 0;

    int p0 = (d0 >= 0) ? atomicAdd(&g_cur[d0], 1) : 0;
    int p1 = (d1 >= 0) ? atomicAdd(&g_cur[d1], 1) : 0;
    int p2 = (d2 >= 0) ? atomicAdd(&g_cur[d2], 1) : 0;
    int p3 = (d3 >= 0) ? atomicAdd(&g_cur[d3], 1) : 0;

    if (d0 >= 0) g_csr[p0] = s0;
    if (d1 >= 0) g_csr[p1] = s1;
    if (d2 >= 0) g_csr[p2] = s2;
    if (d3 >= 0) g_csr[p3] = s3;
}

// ------------------------------------------------------------------
// K5: aggregation, 8-edge batches (compiler-scheduled load batching).
// One warp per dst node; lane owns 4 channels (head = lane>>2).
// ------------------------------------------------------------------
__global__ void k_agg(const float* __restrict__ bias, float* __restrict__ out, int n) {
    int warp = (blockIdx.x * blockDim.x + threadIdx.x) >> 5;
    int lane = threadIdx.x & 31;
    if (warp >= n) return;

    const int h = lane >> 2;
    const float rv = g_right[warp * HH + h];
    const int s0 = g_off[warp], s1 = g_off[warp + 1];
    const unsigned em_off = lane * 4;

    float4 acc = make_float4(0.f, 0.f, 0.f, 0.f);
    float sumw = 0.f;

    for (int base = s0; base < s1; base += 32) {
        int idx = base + lane;
        int sv  = (idx < s1) ? g_csr[idx] : 0;
        int cnt = min(32, s1 - base);

        int j = 0;
        for (; j + 8 <= cnt; j += 8) {
            int   s[8]; float lv[8]; uint2 r[8];
            #pragma unroll
            for (int u = 0; u < 8; u++) s[u] = __shfl_sync(0xffffffffu, sv, j + u);
            #pragma unroll
            for (int u = 0; u < 8; u++) lv[u] = g_left[s[u] * HH + h];
            #pragma unroll
            for (int u = 0; u < 8; u++) r[u] = *(const uint2*)&g_embh[s[u] * CC + em_off];
            #pragma unroll
            for (int u = 0; u < 8; u++) {
                float e = lv[u] + rv;
                e = (e >= 0.f) ? e : 0.2f * e;
                float w = __expf(e);
                float2 f0 = __half22float2(*(__half2*)&r[u].x);
                float2 f1 = __half22float2(*(__half2*)&r[u].y);
                sumw  += w;
                acc.x += w * f0.x; acc.y += w * f0.y;
                acc.z += w * f1.x; acc.w += w * f1.y;
            }
        }
        for (; j < cnt; j++) {
            int s = __shfl_sync(0xffffffffu, sv, j);
            float l = g_left[s * HH + h];
            uint2 raw = *(const uint2*)&g_embh[s * CC + em_off];
            float e = l + rv;
            e = (e >= 0.f) ? e : 0.2f * e;
            float w = __expf(e);
            float2 f0 = __half22float2(*(__half2*)&raw.x);
            float2 f1 = __half22float2(*(__half2*)&raw.y);
            sumw  += w;
            acc.x += w * f0.x; acc.y += w * f0.y;
            acc.z += w * f1.x; acc.w += w * f1.y;
        }
    }

    float inv = (sumw > 0.f) ? (1.f / sumw) : 0.f;
    int c = lane * 4;
    float4 o;
    o.x = acc.x * inv + bias[c + 0];
    o.y = acc.y * inv + bias[c + 1];
    o.z = acc.z * inv + bias[c + 2];
    o.w = acc.w * inv + bias[c + 3];
    *(float4*)&out[warp * CC + c] = o;
}

// ------------------------------------------------------------------
extern "C" void kernel_launch(void* const* d_in, const int* in_sizes, int n_in,
                              void* d_out, int out_size) {
    const float* X    = (const float*)d_in[0];
    const int*   EI   = (const int*)d_in[1];
    const float* W    = (const float*)d_in[2];
    const float* aL   = (const float*)d_in[3];
    const float* aR   = (const float*)d_in[4];
    const float* bias = (const float*)d_in[5];
    float*       out  = (float*)d_out;

    const int n = in_sizes[0] / CC;   // 50000
    const int e = in_sizes[1] / 2;    // 1600000

    const int scatter_threads = (e + 3) / 4;

    k_gemm   <<<(n + 127) / 128, 256>>>(X, W, aL, aR, EI, e, n);
    k_scanA  <<<NBLK, SCAN_B>>>(n);
    k_scanC  <<<NBLK, SCAN_B>>>(n);
    k_scatter<<<(scatter_threads + 255) / 256, 256>>>(EI, e);
    k_agg    <<<(n * 32 + 255) / 256, 256>>>(bias, out, n);
}

// round 16
// speedup vs baseline: 1.0717x; 1.0626x over previous
#include <cuda_runtime.h>
#include <cuda_fp16.h>
#include <cstdint>

#define Nn 50000
#define Ee 1600000
#define CC 128
#define HH 8
#define SCAN_B 1024
#define NBLK ((Nn + SCAN_B - 1) / SCAN_B)   // 49

// ---- scratch (static __device__: allocation-free, zero-initialized) ----
__device__ __half g_embh[Nn * CC];   // 12.8 MB (fp16 message values)
__device__ float g_left[Nn * HH];
__device__ float g_right[Nn * HH];
__device__ int   g_deg[Nn];          // zero at load; re-zeroed by k_scatter each call
__device__ int   g_off[Nn + 1];
__device__ int   g_cur[Nn];
__device__ int   g_csr[Ee];          // 6.4 MB

// ------------------------------------------------------------------
// K1: emb = X @ W^T via mma.sync m16n8k16 (f16 in, f32 acc)
//     + fused left/right logits + fused dst-degree histogram (REDG).
// ------------------------------------------------------------------
__global__ void k_gemm(const float* __restrict__ X, const float* __restrict__ W,
                       const float* __restrict__ aL, const float* __restrict__ aR,
                       const int* __restrict__ ei, int e, int n) {
    __shared__ __half Xsh[128][72];   // stride 72 halves -> conflict-free
    __shared__ __half Wsh[128][72];
    __shared__ float  aLs[16][8];
    __shared__ float  aRs[16][8];

    const int tid  = threadIdx.x;
    const int lane = tid & 31;
    const int wid  = tid >> 5;
    const int q    = lane & 3;
    const int g    = lane >> 2;
    const int m0   = blockIdx.x * 128;

    if (tid < 128) {
        aLs[tid >> 3][tid & 7] = aL[tid];
        aRs[tid >> 3][tid & 7] = aR[tid];
    }

    float acc[16][4];
    #pragma unroll
    for (int nt = 0; nt < 16; nt++) {
        acc[nt][0] = 0.f; acc[nt][1] = 0.f; acc[nt][2] = 0.f; acc[nt][3] = 0.f;
    }

    for (int kc = 0; kc < CC; kc += 64) {
        #pragma unroll
        for (int it = 0; it < 8; it++) {
            int idx = tid + it * 256;
            int r   = idx >> 4;
            int c4  = (idx & 15) * 4;
            int node = m0 + r;
            float4 v = (node < n) ? *(const float4*)&X[node * CC + kc + c4]
                                  : make_float4(0.f, 0.f, 0.f, 0.f);
            *(__half2*)&Xsh[r][c4]     = __floats2half2_rn(v.x, v.y);
            *(__half2*)&Xsh[r][c4 + 2] = __floats2half2_rn(v.z, v.w);
        }
        #pragma unroll
        for (int it = 0; it < 8; it++) {
            int idx = tid + it * 256;
            int r   = idx >> 4;
            int c4  = (idx & 15) * 4;
            float4 v = *(const float4*)&W[r * CC + kc + c4];
            *(__half2*)&Wsh[r][c4]     = __floats2half2_rn(v.x, v.y);
            *(__half2*)&Wsh[r][c4 + 2] = __floats2half2_rn(v.z, v.w);
        }
        __syncthreads();

        #pragma unroll
        for (int ks = 0; ks < 4; ks++) {
            const int kb   = ks * 16;
            const int arow = wid * 16 + g;
            const int kcol = kb + q * 2;
            uint32_t a0 = *(const uint32_t*)&Xsh[arow][kcol];
            uint32_t a1 = *(const uint32_t*)&Xsh[arow + 8][kcol];
            uint32_t a2 = *(const uint32_t*)&Xsh[arow][kcol + 8];
            uint32_t a3 = *(const uint32_t*)&Xsh[arow + 8][kcol + 8];
            #pragma unroll
            for (int nt = 0; nt < 16; nt++) {
                const int brow = nt * 8 + g;
                uint32_t b0 = *(const uint32_t*)&Wsh[brow][kcol];
                uint32_t b1 = *(const uint32_t*)&Wsh[brow][kcol + 8];
                asm volatile(
                    "mma.sync.aligned.m16n8k16.row.col.f32.f16.f16.f32 "
                    "{%0,%1,%2,%3}, {%4,%5,%6,%7}, {%8,%9}, {%0,%1,%2,%3};\n"
                    : "+f"(acc[nt][0]), "+f"(acc[nt][1]), "+f"(acc[nt][2]), "+f"(acc[nt][3])
                    : "r"(a0), "r"(a1), "r"(a2), "r"(a3), "r"(b0), "r"(b1));
            }
        }
        __syncthreads();
    }

    const int r0    = wid * 16 + g;
    const int node0 = m0 + r0;
    const int node1 = node0 + 8;

    #pragma unroll
    for (int nt = 0; nt < 16; nt++) {
        int c = nt * 8 + q * 2;
        if (node0 < n) *(__half2*)&g_embh[node0 * CC + c] = __floats2half2_rn(acc[nt][0], acc[nt][1]);
        if (node1 < n) *(__half2*)&g_embh[node1 * CC + c] = __floats2half2_rn(acc[nt][2], acc[nt][3]);
    }

    float l0v[HH], r0v[HH], l1v[HH], r1v[HH];
    #pragma unroll
    for (int h = 0; h < HH; h++) {
        const int ntA = 2 * h, ntB = 2 * h + 1;
        const int cA = q * 2;
        const int cB = 8 + q * 2;
        float lA = aLs[cA][h],     lA1 = aLs[cA + 1][h];
        float lB = aLs[cB][h],     lB1 = aLs[cB + 1][h];
        float rA = aRs[cA][h],     rA1 = aRs[cA + 1][h];
        float rB = aRs[cB][h],     rB1 = aRs[cB + 1][h];

        float l0 = acc[ntA][0] * lA + acc[ntA][1] * lA1 + acc[ntB][0] * lB + acc[ntB][1] * lB1;
        float r0s = acc[ntA][0] * rA + acc[ntA][1] * rA1 + acc[ntB][0] * rB + acc[ntB][1] * rB1;
        float l1 = acc[ntA][2] * lA + acc[ntA][3] * lA1 + acc[ntB][2] * lB + acc[ntB][3] * lB1;
        float r1s = acc[ntA][2] * rA + acc[ntA][3] * rA1 + acc[ntB][2] * rB + acc[ntB][3] * rB1;

        l0  += __shfl_xor_sync(0xffffffffu, l0, 1);
        l0  += __shfl_xor_sync(0xffffffffu, l0, 2);
        r0s += __shfl_xor_sync(0xffffffffu, r0s, 1);
        r0s += __shfl_xor_sync(0xffffffffu, r0s, 2);
        l1  += __shfl_xor_sync(0xffffffffu, l1, 1);
        l1  += __shfl_xor_sync(0xffffffffu, l1, 2);
        r1s += __shfl_xor_sync(0xffffffffu, r1s, 1);
        r1s += __shfl_xor_sync(0xffffffffu, r1s, 2);

        l0v[h] = l0; r0v[h] = r0s; l1v[h] = l1; r1v[h] = r1s;
    }
    if (node0 < n) {
        *(float2*)&g_left [node0 * HH + 2 * q] = make_float2(l0v[2 * q], l0v[2 * q + 1]);
        *(float2*)&g_right[node0 * HH + 2 * q] = make_float2(r0v[2 * q], r0v[2 * q + 1]);
    }
    if (node1 < n) {
        *(float2*)&g_left [node1 * HH + 2 * q] = make_float2(l1v[2 * q], l1v[2 * q + 1]);
        *(float2*)&g_right[node1 * HH + 2 * q] = make_float2(r1v[2 * q], r1v[2 * q + 1]);
    }

    // ---- fused dst-degree histogram (return discarded -> REDG) ----
    const int stride = gridDim.x * blockDim.x;
    for (int i = blockIdx.x * blockDim.x + tid; i < e; i += stride)
        atomicAdd(&g_deg[ei[e + i]], 1);
}

// ------------------------------------------------------------------
// K3: single-kernel exclusive scan. Block b: carry = reduce of chunks
// 0..b-1 (redundant, cheap: <=48K ints over 1024 threads), then scans
// its own chunk and writes final off/cur. g_deg left INTACT (zeroed in
// k_scatter).
// ------------------------------------------------------------------
__global__ void k_scan(int n) {
    __shared__ int wsums[32];
    __shared__ int carry_sh;
    const int tid = threadIdx.x;
    const int bid = blockIdx.x;
    const int pre = bid * SCAN_B;    // elements before this block

    // ---- reduce predecessors for carry ----
    int partial = 0;
    for (int i = tid; i < pre; i += SCAN_B) partial += g_deg[i];
    #pragma unroll
    for (int d = 16; d > 0; d >>= 1)
        partial += __shfl_xor_sync(0xffffffffu, partial, d);
    if ((tid & 31) == 0) wsums[tid >> 5] = partial;
    __syncthreads();
    if (tid < 32) {
        int s = wsums[tid];
        #pragma unroll
        for (int d = 16; d > 0; d >>= 1)
            s += __shfl_xor_sync(0xffffffffu, s, d);
        if (tid == 0) carry_sh = s;
    }
    __syncthreads();
    const int carry = carry_sh;
    __syncthreads();                  // wsums reused below

    // ---- scan own chunk ----
    int i = pre + tid;
    int v = (i < n) ? g_deg[i] : 0;
    int x = v;
    #pragma unroll
    for (int d = 1; d < 32; d <<= 1) {
        int y = __shfl_up_sync(0xffffffffu, x, d);
        if ((tid & 31) >= d) x += y;
    }
    if ((tid & 31) == 31) wsums[tid >> 5] = x;
    __syncthreads();
    if (tid < 32) {
        int s = wsums[tid];
        #pragma unroll
        for (int d = 1; d < 32; d <<= 1) {
            int y = __shfl_up_sync(0xffffffffu, s, d);
            if (tid >= d) s += y;
        }
        wsums[tid] = s;
    }
    __syncthreads();
    int wp   = (tid >= 32) ? wsums[(tid >> 5) - 1] : 0;
    int incl = x + wp;

    if (i < n) {
        int o = carry + incl - v;
        g_off[i] = o;
        g_cur[i] = o;
    }
    if (bid == NBLK - 1 && tid == SCAN_B - 1) g_off[n] = carry + incl;
}

// ------------------------------------------------------------------
// K4: scatter edges into CSR (by dst), one edge/thread (R12 form),
// plus g_deg re-zero for the next call.
// ------------------------------------------------------------------
__global__ void k_scatter(const int* __restrict__ ei, int e, int n) {
    int i = blockIdx.x * blockDim.x + threadIdx.x;
    if (i < n) g_deg[i] = 0;          // g_deg dead after k_scan; clean for next call
    if (i < e) {
        int dst = ei[e + i];
        int pos = atomicAdd(&g_cur[dst], 1);
        g_csr[pos] = ei[i];
    }
}

// ------------------------------------------------------------------
// K5: aggregation, 8-edge batches (compiler-scheduled load batching).
// One warp per dst node; lane owns 4 channels (head = lane>>2).
// ------------------------------------------------------------------
__global__ void k_agg(const float* __restrict__ bias, float* __restrict__ out, int n) {
    int warp = (blockIdx.x * blockDim.x + threadIdx.x) >> 5;
    int lane = threadIdx.x & 31;
    if (warp >= n) return;

    const int h = lane >> 2;
    const float rv = g_right[warp * HH + h];
    const int s0 = g_off[warp], s1 = g_off[warp + 1];
    const unsigned em_off = lane * 4;

    float4 acc = make_float4(0.f, 0.f, 0.f, 0.f);
    float sumw = 0.f;

    for (int base = s0; base < s1; base += 32) {
        int idx = base + lane;
        int sv  = (idx < s1) ? g_csr[idx] : 0;
        int cnt = min(32, s1 - base);

        int j = 0;
        for (; j + 8 <= cnt; j += 8) {
            int   s[8]; float lv[8]; uint2 r[8];
            #pragma unroll
            for (int u = 0; u < 8; u++) s[u] = __shfl_sync(0xffffffffu, sv, j + u);
            #pragma unroll
            for (int u = 0; u < 8; u++) lv[u] = g_left[s[u] * HH + h];
            #pragma unroll
            for (int u = 0; u < 8; u++) r[u] = *(const uint2*)&g_embh[s[u] * CC + em_off];
            #pragma unroll
            for (int u = 0; u < 8; u++) {
                float e = lv[u] + rv;
                e = (e >= 0.f) ? e : 0.2f * e;
                float w = __expf(e);
                float2 f0 = __half22float2(*(__half2*)&r[u].x);
                float2 f1 = __half22float2(*(__half2*)&r[u].y);
                sumw  += w;
                acc.x += w * f0.x; acc.y += w * f0.y;
                acc.z += w * f1.x; acc.w += w * f1.y;
            }
        }
        for (; j < cnt; j++) {
            int s = __shfl_sync(0xffffffffu, sv, j);
            float l = g_left[s * HH + h];
            uint2 raw = *(const uint2*)&g_embh[s * CC + em_off];
            float e = l + rv;
            e = (e >= 0.f) ? e : 0.2f * e;
            float w = __expf(e);
            float2 f0 = __half22float2(*(__half2*)&raw.x);
            float2 f1 = __half22float2(*(__half2*)&raw.y);
            sumw  += w;
            acc.x += w * f0.x; acc.y += w * f0.y;
            acc.z += w * f1.x; acc.w += w * f1.y;
        }
    }

    float inv = (sumw > 0.f) ? (1.f / sumw) : 0.f;
    int c = lane * 4;
    float4 o;
    o.x = acc.x * inv + bias[c + 0];
    o.y = acc.y * inv + bias[c + 1];
    o.z = acc.z * inv + bias[c + 2];
    o.w = acc.w * inv + bias[c + 3];
    *(float4*)&out[warp * CC + c] = o;
}

// ------------------------------------------------------------------
extern "C" void kernel_launch(void* const* d_in, const int* in_sizes, int n_in,
                              void* d_out, int out_size) {
    const float* X    = (const float*)d_in[0];
    const int*   EI   = (const int*)d_in[1];
    const float* W    = (const float*)d_in[2];
    const float* aL   = (const float*)d_in[3];
    const float* aR   = (const float*)d_in[4];
    const float* bias = (const float*)d_in[5];
    float*       out  = (float*)d_out;

    const int n = in_sizes[0] / CC;   // 50000
    const int e = in_sizes[1] / 2;    // 1600000

    k_gemm   <<<(n + 127) / 128, 256>>>(X, W, aL, aR, EI, e, n);
    k_scan   <<<NBLK, SCAN_B>>>(n);
    k_scatter<<<(e + 255) / 256, 256>>>(EI, e, n);
    k_agg    <<<(n * 32 + 255) / 256, 256>>>(bias, out, n);
}